// round 1
// baseline (speedup 1.0000x reference)
#include <cuda_runtime.h>
#include <cuda_bf16.h>
#include <cstdint>

// BarycentricInterpolator: out[b, m] = sum_k f[b, tri[m,k]] * w[m,k]
// B=128, N=10000, M=500000 (derived at runtime; fallback for odd shapes).
//
// Strategy:
//  * pack kernel: tri_idx + bary_weights -> 16B records {u16 i0,i1,i2; f32 w0,w1}
//    (w2 = 1 - w0 - w1, weights sum to 1)
//  * main kernel: grid = linearized (b-group, m) space split contiguously over
//    2*SM blocks. Each block stages BB=4 f-rows interleaved as float4[N] in
//    shared memory (160 KB), then streams its m-range: 1 coalesced 16B record
//    load + 3 LDS.128 gathers + 4 float2 streaming stores per 2 outputs-of-4.

#define BB 4
#define MAX_M 600000

__device__ __align__(16) uint4 g_recs[MAX_M];   // 9.6 MB scratch (static, no alloc)

__global__ void pack_kernel(const int* __restrict__ tri,
                            const float* __restrict__ w,
                            int M) {
    int m = blockIdx.x * blockDim.x + threadIdx.x;
    if (m >= M) return;
    unsigned i0 = (unsigned)tri[3 * m + 0];
    unsigned i1 = (unsigned)tri[3 * m + 1];
    unsigned i2 = (unsigned)tri[3 * m + 2];
    float w0 = w[3 * m + 0];
    float w1 = w[3 * m + 1];
    uint4 r;
    r.x = (i0 & 0xFFFFu) | (i1 << 16);
    r.y = i2 & 0xFFFFu;
    r.z = __float_as_uint(w0);
    r.w = __float_as_uint(w1);
    g_recs[m] = r;
}

__global__ void __launch_bounds__(512, 1)
interp_kernel(const float* __restrict__ f,
              float* __restrict__ out,
              int Bv, int Nv, int Mv) {
    extern __shared__ float fsh[];                 // BB * Nv floats, [i][bl] interleaved
    const float4* __restrict__ fs4 = reinterpret_cast<const float4*>(fsh);

    const int NB = Bv / BB;                        // 32 b-groups
    const long long J = (long long)NB * (long long)Mv;

    long long j0 = (long long)blockIdx.x * J / gridDim.x;
    long long j1 = (long long)(blockIdx.x + 1) * J / gridDim.x;
    // keep all m boundaries even (Mv is even) so float2 stores stay 8B-aligned
    j0 &= ~1LL;
    if (blockIdx.x + 1 != gridDim.x) j1 &= ~1LL;

    long long j = j0;
    while (j < j1) {
        const int gb = (int)(j / Mv);
        const long long seg_end = min(j1, (long long)(gb + 1) * (long long)Mv);

        // ---- stage BB rows of f into smem, interleaved [i*BB + bl] ----
        {
            const float* frow = f + (long long)gb * BB * Nv;
            const int tot = BB * Nv;
            for (int t = threadIdx.x; t < tot; t += blockDim.x) {
                int bl = t / Nv;
                int i  = t - bl * Nv;
                fsh[i * BB + bl] = frow[(long long)bl * Nv + i];
            }
        }
        __syncthreads();

        const int m_lo = (int)(j - (long long)gb * Mv);
        const int m_hi = (int)(seg_end - (long long)gb * Mv);
        float* __restrict__ outb = out + (long long)gb * BB * Mv;

        int m = m_lo + 2 * (int)threadIdx.x;
        #pragma unroll 2
        for (; m + 1 < m_hi; m += 2 * (int)blockDim.x) {
            uint4 r0 = g_recs[m];
            uint4 r1 = g_recs[m + 1];

            float4 a0 = fs4[r0.x & 0xFFFFu];
            float4 b0 = fs4[r0.x >> 16];
            float4 c0 = fs4[r0.y & 0xFFFFu];
            float4 a1 = fs4[r1.x & 0xFFFFu];
            float4 b1 = fs4[r1.x >> 16];
            float4 c1 = fs4[r1.y & 0xFFFFu];

            float w00 = __uint_as_float(r0.z);
            float w01 = __uint_as_float(r0.w);
            float w02 = 1.0f - w00 - w01;
            float w10 = __uint_as_float(r1.z);
            float w11 = __uint_as_float(r1.w);
            float w12 = 1.0f - w10 - w11;

            float* o = outb + m;
            __stcs(reinterpret_cast<float2*>(o),
                   make_float2(w00 * a0.x + w01 * b0.x + w02 * c0.x,
                               w10 * a1.x + w11 * b1.x + w12 * c1.x));
            __stcs(reinterpret_cast<float2*>(o + Mv),
                   make_float2(w00 * a0.y + w01 * b0.y + w02 * c0.y,
                               w10 * a1.y + w11 * b1.y + w12 * c1.y));
            __stcs(reinterpret_cast<float2*>(o + 2 * Mv),
                   make_float2(w00 * a0.z + w01 * b0.z + w02 * c0.z,
                               w10 * a1.z + w11 * b1.z + w12 * c1.z));
            __stcs(reinterpret_cast<float2*>(o + 3 * Mv),
                   make_float2(w00 * a0.w + w01 * b0.w + w02 * c0.w,
                               w10 * a1.w + w11 * b1.w + w12 * c1.w));
        }
        // robustness tail (unused when ranges are even-sized)
        if (m < m_hi) {
            uint4 r0 = g_recs[m];
            float4 a0 = fs4[r0.x & 0xFFFFu];
            float4 b0 = fs4[r0.x >> 16];
            float4 c0 = fs4[r0.y & 0xFFFFu];
            float w00 = __uint_as_float(r0.z);
            float w01 = __uint_as_float(r0.w);
            float w02 = 1.0f - w00 - w01;
            float* o = outb + m;
            __stcs(o,          w00 * a0.x + w01 * b0.x + w02 * c0.x);
            __stcs(o + Mv,     w00 * a0.y + w01 * b0.y + w02 * c0.y);
            __stcs(o + 2 * Mv, w00 * a0.z + w01 * b0.z + w02 * c0.z);
            __stcs(o + 3 * Mv, w00 * a0.w + w01 * b0.w + w02 * c0.w);
        }
        __syncthreads();
        j = seg_end;
    }
}

// Fallback for shapes the fast path can't handle.
__global__ void naive_kernel(const float* __restrict__ f,
                             const int* __restrict__ tri,
                             const float* __restrict__ w,
                             float* __restrict__ out,
                             int B, int N, int M) {
    int m = blockIdx.x * blockDim.x + threadIdx.x;
    if (m >= M) return;
    int i0 = tri[3 * m], i1 = tri[3 * m + 1], i2 = tri[3 * m + 2];
    float w0 = w[3 * m], w1 = w[3 * m + 1], w2 = w[3 * m + 2];
    for (int b = 0; b < B; b++) {
        out[(long long)b * M + m] =
            w0 * f[(long long)b * N + i0] +
            w1 * f[(long long)b * N + i1] +
            w2 * f[(long long)b * N + i2];
    }
}

extern "C" void kernel_launch(void* const* d_in, const int* in_sizes, int n_in,
                              void* d_out, int out_size) {
    const float* f   = (const float*)d_in[0];
    const int*   tri = (const int*)d_in[1];
    const float* w   = (const float*)d_in[2];
    float* out = (float*)d_out;

    const int M = in_sizes[1] / 3;
    const int B = out_size / M;
    const int N = in_sizes[0] / B;

    const bool fast = (B % BB == 0) && (N < 65536) && (N <= 14500) &&
                      (M <= MAX_M) && (M % 2 == 0);

    if (!fast) {
        naive_kernel<<<(M + 255) / 256, 256>>>(f, tri, w, out, B, N, M);
        return;
    }

    pack_kernel<<<(M + 255) / 256, 256>>>(tri, w, M);

    int sms = 148;
    cudaDeviceGetAttribute(&sms, cudaDevAttrMultiProcessorCount, 0);

    const int smem_bytes = BB * N * (int)sizeof(float);
    cudaFuncSetAttribute(interp_kernel,
                         cudaFuncAttributeMaxDynamicSharedMemorySize, smem_bytes);

    const int grid = 2 * sms;
    interp_kernel<<<grid, 512, smem_bytes>>>(f, out, B, N, M);
}

// round 2
// speedup vs baseline: 1.0730x; 1.0730x over previous
#include <cuda_runtime.h>
#include <cuda_bf16.h>
#include <cstdint>

// BarycentricInterpolator: out[b, m] = sum_k f[b, tri[m,k]] * w[m,k]
// B=128, N=10000, M=500000.
//
// R2 changes vs R1 (168.9us, occ 25%, issue 17% -> latency-bound):
//  * 1024 threads/block (32 warps/SM, occ 50%)
//  * 4 m per thread per iteration: 4 independent record LDG.128 (MLP=4),
//    12 LDS.128 gathers, 4 STG.128 stores (m 4-aligned)

#define BB 4
#define MAX_M 600000

__device__ __align__(16) uint4 g_recs[MAX_M];   // packed {u16 i0,i1,i2; f32 w0,w1}

__global__ void pack_kernel(const int* __restrict__ tri,
                            const float* __restrict__ w,
                            int M) {
    int m = blockIdx.x * blockDim.x + threadIdx.x;
    if (m >= M) return;
    unsigned i0 = (unsigned)tri[3 * m + 0];
    unsigned i1 = (unsigned)tri[3 * m + 1];
    unsigned i2 = (unsigned)tri[3 * m + 2];
    float w0 = w[3 * m + 0];
    float w1 = w[3 * m + 1];
    uint4 r;
    r.x = (i0 & 0xFFFFu) | (i1 << 16);
    r.y = i2 & 0xFFFFu;
    r.z = __float_as_uint(w0);
    r.w = __float_as_uint(w1);
    g_recs[m] = r;
}

__device__ __forceinline__ float4 bary3(float4 a, float4 b, float4 c,
                                        float w0, float w1, float w2) {
    float4 r;
    r.x = w0 * a.x + w1 * b.x + w2 * c.x;
    r.y = w0 * a.y + w1 * b.y + w2 * c.y;
    r.z = w0 * a.z + w1 * b.z + w2 * c.z;
    r.w = w0 * a.w + w1 * b.w + w2 * c.w;
    return r;
}

__global__ void __launch_bounds__(1024, 1)
interp_kernel(const float* __restrict__ f,
              float* __restrict__ out,
              int Bv, int Nv, int Mv) {
    extern __shared__ float fsh[];                 // BB * Nv floats, [i][bl] interleaved
    const float4* __restrict__ fs4 = reinterpret_cast<const float4*>(fsh);

    const int NB = Bv / BB;                        // 32 b-groups
    const long long J = (long long)NB * (long long)Mv;

    long long j0 = (long long)blockIdx.x * J / gridDim.x;
    long long j1 = (long long)(blockIdx.x + 1) * J / gridDim.x;
    // keep all m boundaries multiple of 4 (Mv % 4 == 0) for STG.128 alignment
    j0 &= ~3LL;
    if (blockIdx.x + 1 != gridDim.x) j1 &= ~3LL;

    long long j = j0;
    while (j < j1) {
        const int gb = (int)(j / Mv);
        const long long seg_end = min(j1, (long long)(gb + 1) * (long long)Mv);

        // ---- stage BB rows of f into smem, interleaved [i*BB + bl] ----
        {
            const float* frow = f + (long long)gb * BB * Nv;
            const int tot = BB * Nv;
            for (int t = threadIdx.x; t < tot; t += blockDim.x) {
                int bl = t / Nv;
                int i  = t - bl * Nv;
                fsh[i * BB + bl] = frow[(long long)bl * Nv + i];
            }
        }
        __syncthreads();

        const int m_lo = (int)(j - (long long)gb * Mv);
        const int m_hi = (int)(seg_end - (long long)gb * Mv);
        float* __restrict__ outb = out + (long long)gb * BB * Mv;

        int m = m_lo + 4 * (int)threadIdx.x;
        const int stride = 4 * (int)blockDim.x;
        #pragma unroll 2
        for (; m + 3 < m_hi; m += stride) {
            // 4 independent record loads -> MLP=4 on the L2 latency
            uint4 r0 = g_recs[m];
            uint4 r1 = g_recs[m + 1];
            uint4 r2 = g_recs[m + 2];
            uint4 r3 = g_recs[m + 3];

            float4 a0 = fs4[r0.x & 0xFFFFu], b0 = fs4[r0.x >> 16], c0 = fs4[r0.y & 0xFFFFu];
            float4 a1 = fs4[r1.x & 0xFFFFu], b1 = fs4[r1.x >> 16], c1 = fs4[r1.y & 0xFFFFu];
            float4 a2 = fs4[r2.x & 0xFFFFu], b2 = fs4[r2.x >> 16], c2 = fs4[r2.y & 0xFFFFu];
            float4 a3 = fs4[r3.x & 0xFFFFu], b3 = fs4[r3.x >> 16], c3 = fs4[r3.y & 0xFFFFu];

            float w00 = __uint_as_float(r0.z), w01 = __uint_as_float(r0.w);
            float w10 = __uint_as_float(r1.z), w11 = __uint_as_float(r1.w);
            float w20 = __uint_as_float(r2.z), w21 = __uint_as_float(r2.w);
            float w30 = __uint_as_float(r3.z), w31 = __uint_as_float(r3.w);

            float4 s0 = bary3(a0, b0, c0, w00, w01, 1.0f - w00 - w01);
            float4 s1 = bary3(a1, b1, c1, w10, w11, 1.0f - w10 - w11);
            float4 s2 = bary3(a2, b2, c2, w20, w21, 1.0f - w20 - w21);
            float4 s3 = bary3(a3, b3, c3, w30, w31, 1.0f - w30 - w31);

            float* o = outb + m;
            __stcs(reinterpret_cast<float4*>(o),
                   make_float4(s0.x, s1.x, s2.x, s3.x));
            __stcs(reinterpret_cast<float4*>(o + Mv),
                   make_float4(s0.y, s1.y, s2.y, s3.y));
            __stcs(reinterpret_cast<float4*>(o + 2 * Mv),
                   make_float4(s0.z, s1.z, s2.z, s3.z));
            __stcs(reinterpret_cast<float4*>(o + 3 * Mv),
                   make_float4(s0.w, s1.w, s2.w, s3.w));
        }
        // robustness tail (unused when ranges are 4-aligned)
        for (; m < m_hi; m++) {
            uint4 r0 = g_recs[m];
            float4 a0 = fs4[r0.x & 0xFFFFu];
            float4 b0 = fs4[r0.x >> 16];
            float4 c0 = fs4[r0.y & 0xFFFFu];
            float w00 = __uint_as_float(r0.z);
            float w01 = __uint_as_float(r0.w);
            float w02 = 1.0f - w00 - w01;
            float* o = outb + m;
            __stcs(o,          w00 * a0.x + w01 * b0.x + w02 * c0.x);
            __stcs(o + Mv,     w00 * a0.y + w01 * b0.y + w02 * c0.y);
            __stcs(o + 2 * Mv, w00 * a0.z + w01 * b0.z + w02 * c0.z);
            __stcs(o + 3 * Mv, w00 * a0.w + w01 * b0.w + w02 * c0.w);
        }
        __syncthreads();
        j = seg_end;
    }
}

// Fallback for shapes the fast path can't handle.
__global__ void naive_kernel(const float* __restrict__ f,
                             const int* __restrict__ tri,
                             const float* __restrict__ w,
                             float* __restrict__ out,
                             int B, int N, int M) {
    int m = blockIdx.x * blockDim.x + threadIdx.x;
    if (m >= M) return;
    int i0 = tri[3 * m], i1 = tri[3 * m + 1], i2 = tri[3 * m + 2];
    float w0 = w[3 * m], w1 = w[3 * m + 1], w2 = w[3 * m + 2];
    for (int b = 0; b < B; b++) {
        out[(long long)b * M + m] =
            w0 * f[(long long)b * N + i0] +
            w1 * f[(long long)b * N + i1] +
            w2 * f[(long long)b * N + i2];
    }
}

extern "C" void kernel_launch(void* const* d_in, const int* in_sizes, int n_in,
                              void* d_out, int out_size) {
    const float* f   = (const float*)d_in[0];
    const int*   tri = (const int*)d_in[1];
    const float* w   = (const float*)d_in[2];
    float* out = (float*)d_out;

    const int M = in_sizes[1] / 3;
    const int B = out_size / M;
    const int N = in_sizes[0] / B;

    const bool fast = (B % BB == 0) && (N < 65536) && (N <= 14000) &&
                      (M <= MAX_M) && (M % 4 == 0);

    if (!fast) {
        naive_kernel<<<(M + 255) / 256, 256>>>(f, tri, w, out, B, N, M);
        return;
    }

    pack_kernel<<<(M + 255) / 256, 256>>>(tri, w, M);

    int sms = 148;
    cudaDeviceGetAttribute(&sms, cudaDevAttrMultiProcessorCount, 0);

    const int smem_bytes = BB * N * (int)sizeof(float);
    cudaFuncSetAttribute(interp_kernel,
                         cudaFuncAttributeMaxDynamicSharedMemorySize, smem_bytes);

    const int grid = 2 * sms;   // two balanced waves, 1 block/SM resident
    interp_kernel<<<grid, 1024, smem_bytes>>>(f, out, B, N, M);
}

// round 3
// speedup vs baseline: 1.0842x; 1.0105x over previous
#include <cuda_runtime.h>
#include <cuda_fp16.h>
#include <cstdint>

// BarycentricInterpolator: out[b, m] = sum_k f[b, tri[m,k]] * w[m,k]
// B=128, N=10000, M=500000.
//
// R3: fp16 f-tiles in smem, BB=8 rows per pass (160 KB). Halves LDS wavefronts,
// record LDG traffic, and pass count vs R2 (fp32 BB=4). Math in fp32.

#define BB 8
#define MAX_M 600000

__device__ __align__(16) uint4 g_recs[MAX_M];   // packed {u16 i0,i1,i2; f32 w0,w1}

__global__ void pack_kernel(const int* __restrict__ tri,
                            const float* __restrict__ w,
                            int M) {
    int m = blockIdx.x * blockDim.x + threadIdx.x;
    if (m >= M) return;
    unsigned i0 = (unsigned)tri[3 * m + 0];
    unsigned i1 = (unsigned)tri[3 * m + 1];
    unsigned i2 = (unsigned)tri[3 * m + 2];
    float w0 = w[3 * m + 0];
    float w1 = w[3 * m + 1];
    uint4 r;
    r.x = (i0 & 0xFFFFu) | (i1 << 16);
    r.y = i2 & 0xFFFFu;
    r.z = __float_as_uint(w0);
    r.w = __float_as_uint(w1);
    g_recs[m] = r;
}

// 4 consecutive fp16 b-values -> float4
__device__ __forceinline__ float4 h4_to_f4(uint2 g) {
    float2 lo = __half22float2(*reinterpret_cast<__half2*>(&g.x));
    float2 hi = __half22float2(*reinterpret_cast<__half2*>(&g.y));
    return make_float4(lo.x, lo.y, hi.x, hi.y);
}

__global__ void __launch_bounds__(1024, 1)
interp_kernel(const float* __restrict__ f,
              float* __restrict__ out,
              int Bv, int Nv, int Mv) {
    extern __shared__ __half fsh[];                 // BB * Nv halves, fsh[i*8 + bl]
    const uint2* __restrict__ fs2 = reinterpret_cast<const uint2*>(fsh);

    const int NB = Bv / BB;                         // 16 b-groups
    const long long J = (long long)NB * (long long)Mv;

    long long j0 = (long long)blockIdx.x * J / gridDim.x;
    long long j1 = (long long)(blockIdx.x + 1) * J / gridDim.x;
    j0 &= ~3LL;                                     // STG.128 alignment (Mv % 4 == 0)
    if (blockIdx.x + 1 != gridDim.x) j1 &= ~3LL;

    long long j = j0;
    while (j < j1) {
        const int gb = (int)(j / Mv);
        const long long seg_end = min(j1, (long long)(gb + 1) * (long long)Mv);

        // ---- stage BB rows of f into smem as fp16, interleaved [i*8 + bl] ----
        {
            const float* frow = f + (long long)gb * BB * Nv;
            const int tot = BB * Nv;
            for (int t = threadIdx.x; t < tot; t += blockDim.x) {
                int bl = t / Nv;
                int i  = t - bl * Nv;
                fsh[i * BB + bl] = __float2half_rn(frow[(long long)bl * Nv + i]);
            }
        }
        __syncthreads();

        const int m_lo = (int)(j - (long long)gb * Mv);
        const int m_hi = (int)(seg_end - (long long)gb * Mv);
        float* __restrict__ outb = out + (long long)gb * BB * Mv;

        int m = m_lo + 4 * (int)threadIdx.x;
        const int stride = 4 * (int)blockDim.x;
        for (; m + 3 < m_hi; m += stride) {
            // 4 independent record loads (L2-resident; .cg = no L1 alloc)
            uint4 r0 = __ldcg(&g_recs[m]);
            uint4 r1 = __ldcg(&g_recs[m + 1]);
            uint4 r2 = __ldcg(&g_recs[m + 2]);
            uint4 r3 = __ldcg(&g_recs[m + 3]);

            const int i00 = r0.x & 0xFFFFu, i01 = r0.x >> 16, i02 = r0.y & 0xFFFFu;
            const int i10 = r1.x & 0xFFFFu, i11 = r1.x >> 16, i12 = r1.y & 0xFFFFu;
            const int i20 = r2.x & 0xFFFFu, i21 = r2.x >> 16, i22 = r2.y & 0xFFFFu;
            const int i30 = r3.x & 0xFFFFu, i31 = r3.x >> 16, i32 = r3.y & 0xFFFFu;

            const float w00 = __uint_as_float(r0.z), w01 = __uint_as_float(r0.w);
            const float w10 = __uint_as_float(r1.z), w11 = __uint_as_float(r1.w);
            const float w20 = __uint_as_float(r2.z), w21 = __uint_as_float(r2.w);
            const float w30 = __uint_as_float(r3.z), w31 = __uint_as_float(r3.w);
            const float w02 = 1.0f - w00 - w01;
            const float w12 = 1.0f - w10 - w11;
            const float w22 = 1.0f - w20 - w21;
            const float w32 = 1.0f - w30 - w31;

            #pragma unroll
            for (int h = 0; h < 2; h++) {
                // acc{b}: float4 over m..m+3 for b_local = 0..3 of this half
                float4 acc0, acc1, acc2, acc3;

                // k = 0 (m)
                {
                    float4 va = h4_to_f4(fs2[i00 * 2 + h]);
                    float4 vb = h4_to_f4(fs2[i01 * 2 + h]);
                    float4 vc = h4_to_f4(fs2[i02 * 2 + h]);
                    acc0.x = fmaf(w00, va.x, fmaf(w01, vb.x, w02 * vc.x));
                    acc1.x = fmaf(w00, va.y, fmaf(w01, vb.y, w02 * vc.y));
                    acc2.x = fmaf(w00, va.z, fmaf(w01, vb.z, w02 * vc.z));
                    acc3.x = fmaf(w00, va.w, fmaf(w01, vb.w, w02 * vc.w));
                }
                // k = 1 (m+1)
                {
                    float4 va = h4_to_f4(fs2[i10 * 2 + h]);
                    float4 vb = h4_to_f4(fs2[i11 * 2 + h]);
                    float4 vc = h4_to_f4(fs2[i12 * 2 + h]);
                    acc0.y = fmaf(w10, va.x, fmaf(w11, vb.x, w12 * vc.x));
                    acc1.y = fmaf(w10, va.y, fmaf(w11, vb.y, w12 * vc.y));
                    acc2.y = fmaf(w10, va.z, fmaf(w11, vb.z, w12 * vc.z));
                    acc3.y = fmaf(w10, va.w, fmaf(w11, vb.w, w12 * vc.w));
                }
                // k = 2 (m+2)
                {
                    float4 va = h4_to_f4(fs2[i20 * 2 + h]);
                    float4 vb = h4_to_f4(fs2[i21 * 2 + h]);
                    float4 vc = h4_to_f4(fs2[i22 * 2 + h]);
                    acc0.z = fmaf(w20, va.x, fmaf(w21, vb.x, w22 * vc.x));
                    acc1.z = fmaf(w20, va.y, fmaf(w21, vb.y, w22 * vc.y));
                    acc2.z = fmaf(w20, va.z, fmaf(w21, vb.z, w22 * vc.z));
                    acc3.z = fmaf(w20, va.w, fmaf(w21, vb.w, w22 * vc.w));
                }
                // k = 3 (m+3)
                {
                    float4 va = h4_to_f4(fs2[i30 * 2 + h]);
                    float4 vb = h4_to_f4(fs2[i31 * 2 + h]);
                    float4 vc = h4_to_f4(fs2[i32 * 2 + h]);
                    acc0.w = fmaf(w30, va.x, fmaf(w31, vb.x, w32 * vc.x));
                    acc1.w = fmaf(w30, va.y, fmaf(w31, vb.y, w32 * vc.y));
                    acc2.w = fmaf(w30, va.z, fmaf(w31, vb.z, w32 * vc.z));
                    acc3.w = fmaf(w30, va.w, fmaf(w31, vb.w, w32 * vc.w));
                }

                float* o = outb + (long long)(h * 4) * Mv + m;
                __stcs(reinterpret_cast<float4*>(o),          acc0);
                __stcs(reinterpret_cast<float4*>(o + Mv),     acc1);
                __stcs(reinterpret_cast<float4*>(o + 2 * Mv), acc2);
                __stcs(reinterpret_cast<float4*>(o + 3 * Mv), acc3);
            }
        }
        // robustness tail (ranges are 4-aligned in practice)
        for (; m < m_hi; m++) {
            uint4 r0 = __ldcg(&g_recs[m]);
            const int i00 = r0.x & 0xFFFFu, i01 = r0.x >> 16, i02 = r0.y & 0xFFFFu;
            const float w00 = __uint_as_float(r0.z), w01 = __uint_as_float(r0.w);
            const float w02 = 1.0f - w00 - w01;
            #pragma unroll
            for (int h = 0; h < 2; h++) {
                float4 va = h4_to_f4(fs2[i00 * 2 + h]);
                float4 vb = h4_to_f4(fs2[i01 * 2 + h]);
                float4 vc = h4_to_f4(fs2[i02 * 2 + h]);
                float* o = outb + (long long)(h * 4) * Mv + m;
                __stcs(o,          fmaf(w00, va.x, fmaf(w01, vb.x, w02 * vc.x)));
                __stcs(o + Mv,     fmaf(w00, va.y, fmaf(w01, vb.y, w02 * vc.y)));
                __stcs(o + 2 * Mv, fmaf(w00, va.z, fmaf(w01, vb.z, w02 * vc.z)));
                __stcs(o + 3 * Mv, fmaf(w00, va.w, fmaf(w01, vb.w, w02 * vc.w)));
            }
        }
        __syncthreads();
        j = seg_end;
    }
}

// Exact-fp32 fallback for shapes the fast path can't handle.
__global__ void naive_kernel(const float* __restrict__ f,
                             const int* __restrict__ tri,
                             const float* __restrict__ w,
                             float* __restrict__ out,
                             int B, int N, int M) {
    int m = blockIdx.x * blockDim.x + threadIdx.x;
    if (m >= M) return;
    int i0 = tri[3 * m], i1 = tri[3 * m + 1], i2 = tri[3 * m + 2];
    float w0 = w[3 * m], w1 = w[3 * m + 1], w2 = w[3 * m + 2];
    for (int b = 0; b < B; b++) {
        out[(long long)b * M + m] =
            w0 * f[(long long)b * N + i0] +
            w1 * f[(long long)b * N + i1] +
            w2 * f[(long long)b * N + i2];
    }
}

extern "C" void kernel_launch(void* const* d_in, const int* in_sizes, int n_in,
                              void* d_out, int out_size) {
    const float* f   = (const float*)d_in[0];
    const int*   tri = (const int*)d_in[1];
    const float* w   = (const float*)d_in[2];
    float* out = (float*)d_out;

    const int M = in_sizes[1] / 3;
    const int B = out_size / M;
    const int N = in_sizes[0] / B;

    const bool fast = (B % BB == 0) && (N <= 14000) &&
                      (M <= MAX_M) && (M % 4 == 0);

    if (!fast) {
        naive_kernel<<<(M + 255) / 256, 256>>>(f, tri, w, out, B, N, M);
        return;
    }

    pack_kernel<<<(M + 255) / 256, 256>>>(tri, w, M);

    int sms = 148;
    cudaDeviceGetAttribute(&sms, cudaDevAttrMultiProcessorCount, 0);

    const int smem_bytes = BB * N * (int)sizeof(__half);   // 160 KB at N=10000
    cudaFuncSetAttribute(interp_kernel,
                         cudaFuncAttributeMaxDynamicSharedMemorySize, smem_bytes);

    const int grid = 2 * sms;   // two balanced waves, 1 block/SM resident
    interp_kernel<<<grid, 1024, smem_bytes>>>(f, out, B, N, M);
}

// round 4
// speedup vs baseline: 1.3529x; 1.2478x over previous
#include <cuda_runtime.h>
#include <cuda_fp16.h>
#include <cstdint>

// BarycentricInterpolator: out[b, m] = sum_k f[b, tri[m,k]] * w[m,k]
// B=128, N=10000, M=500000.
//
// R4: half2 end-to-end math + 75% occupancy.
//  * f staged in smem as fp16, BB=4 rows (80 KB) -> 2 blocks/SM x 768 thr = 48 warps
//  * records carry pre-broadcast half2 weights; inner loop is pure LDS.64 + HFMA2
//  * fp32 conversion only at the 16 output values per iteration (STG.128)

#define BB 4
#define MAX_M 600000

__device__ __align__(16) uint4 g_recs[MAX_M];
// record: x = i0 | i1<<16 ; y = i2 | h(w2)<<16 ; z = h2(w0,w0) ; w = h2(w1,w1)

__global__ void pack_kernel(const int* __restrict__ tri,
                            const float* __restrict__ w,
                            int M) {
    int m = blockIdx.x * blockDim.x + threadIdx.x;
    if (m >= M) return;
    unsigned i0 = (unsigned)tri[3 * m + 0];
    unsigned i1 = (unsigned)tri[3 * m + 1];
    unsigned i2 = (unsigned)tri[3 * m + 2];
    float w0 = w[3 * m + 0];
    float w1 = w[3 * m + 1];
    float w2 = 1.0f - w0 - w1;
    unsigned h0 = (unsigned)__half_as_ushort(__float2half_rn(w0));
    unsigned h1 = (unsigned)__half_as_ushort(__float2half_rn(w1));
    unsigned h2 = (unsigned)__half_as_ushort(__float2half_rn(w2));
    uint4 r;
    r.x = (i0 & 0xFFFFu) | (i1 << 16);
    r.y = (i2 & 0xFFFFu) | (h2 << 16);
    r.z = h0 | (h0 << 16);
    r.w = h1 | (h1 << 16);
    g_recs[m] = r;
}

__device__ __forceinline__ __half2 u2h(unsigned u) {
    return *reinterpret_cast<__half2*>(&u);
}

__global__ void __launch_bounds__(768, 2)
interp_kernel(const float* __restrict__ f,
              float* __restrict__ out,
              int Bv, int Nv, int Mv) {
    extern __shared__ __half fsh[];                 // BB * Nv halves, fsh[i*4 + bl]
    const uint2* __restrict__ fs2 = reinterpret_cast<const uint2*>(fsh);

    const int NB = Bv / BB;                         // 32 b-groups
    const long long J = (long long)NB * (long long)Mv;

    long long j0 = (long long)blockIdx.x * J / gridDim.x;
    long long j1 = (long long)(blockIdx.x + 1) * J / gridDim.x;
    j0 &= ~3LL;                                     // STG.128 alignment (Mv % 4 == 0)
    if (blockIdx.x + 1 != gridDim.x) j1 &= ~3LL;

    long long j = j0;
    while (j < j1) {
        const int gb = (int)(j / Mv);
        const long long seg_end = min(j1, (long long)(gb + 1) * (long long)Mv);

        // ---- stage BB rows of f into smem as fp16, interleaved [i*4 + bl] ----
        {
            const float* frow = f + (long long)gb * BB * Nv;
            const int tot = BB * Nv;
            for (int t = threadIdx.x; t < tot; t += blockDim.x) {
                int bl = t / Nv;
                int i  = t - bl * Nv;
                fsh[i * BB + bl] = __float2half_rn(frow[(long long)bl * Nv + i]);
            }
        }
        __syncthreads();

        const int m_lo = (int)(j - (long long)gb * Mv);
        const int m_hi = (int)(seg_end - (long long)gb * Mv);
        float* __restrict__ outb = out + (long long)gb * BB * Mv;

        int m = m_lo + 4 * (int)threadIdx.x;
        const int stride = 4 * (int)blockDim.x;
        for (; m + 3 < m_hi; m += stride) {
            uint4 r[4];
            r[0] = __ldcg(&g_recs[m]);
            r[1] = __ldcg(&g_recs[m + 1]);
            r[2] = __ldcg(&g_recs[m + 2]);
            r[3] = __ldcg(&g_recs[m + 3]);

            __half2 accA[4];   // b-pair {0,1} for m..m+3
            __half2 accB[4];   // b-pair {2,3}

            #pragma unroll
            for (int k = 0; k < 4; k++) {
                const int i0 = r[k].x & 0xFFFFu;
                const int i1 = r[k].x >> 16;
                const int i2 = r[k].y & 0xFFFFu;
                const __half2 w0 = u2h(r[k].z);
                const __half2 w1 = u2h(r[k].w);
                const __half2 w2 = __half2half2(__ushort_as_half((unsigned short)(r[k].y >> 16)));

                uint2 va = fs2[i0];
                uint2 vb = fs2[i1];
                uint2 vc = fs2[i2];

                accA[k] = __hfma2(w0, u2h(va.x),
                          __hfma2(w1, u2h(vb.x), __hmul2(w2, u2h(vc.x))));
                accB[k] = __hfma2(w0, u2h(va.y),
                          __hfma2(w1, u2h(vb.y), __hmul2(w2, u2h(vc.y))));
            }

            float* o = outb + m;
            __stcs(reinterpret_cast<float4*>(o),
                   make_float4(__low2float(accA[0]),  __low2float(accA[1]),
                               __low2float(accA[2]),  __low2float(accA[3])));
            __stcs(reinterpret_cast<float4*>(o + Mv),
                   make_float4(__high2float(accA[0]), __high2float(accA[1]),
                               __high2float(accA[2]), __high2float(accA[3])));
            __stcs(reinterpret_cast<float4*>(o + 2 * Mv),
                   make_float4(__low2float(accB[0]),  __low2float(accB[1]),
                               __low2float(accB[2]),  __low2float(accB[3])));
            __stcs(reinterpret_cast<float4*>(o + 3 * Mv),
                   make_float4(__high2float(accB[0]), __high2float(accB[1]),
                               __high2float(accB[2]), __high2float(accB[3])));
        }
        // robustness tail (ranges are 4-aligned in practice)
        for (; m < m_hi; m++) {
            uint4 rr = __ldcg(&g_recs[m]);
            const int i0 = rr.x & 0xFFFFu;
            const int i1 = rr.x >> 16;
            const int i2 = rr.y & 0xFFFFu;
            const __half2 w0 = u2h(rr.z);
            const __half2 w1 = u2h(rr.w);
            const __half2 w2 = __half2half2(__ushort_as_half((unsigned short)(rr.y >> 16)));
            uint2 va = fs2[i0];
            uint2 vb = fs2[i1];
            uint2 vc = fs2[i2];
            __half2 sA = __hfma2(w0, u2h(va.x), __hfma2(w1, u2h(vb.x), __hmul2(w2, u2h(vc.x))));
            __half2 sB = __hfma2(w0, u2h(va.y), __hfma2(w1, u2h(vb.y), __hmul2(w2, u2h(vc.y))));
            float* o = outb + m;
            __stcs(o,          __low2float(sA));
            __stcs(o + Mv,     __high2float(sA));
            __stcs(o + 2 * Mv, __low2float(sB));
            __stcs(o + 3 * Mv, __high2float(sB));
        }
        __syncthreads();
        j = seg_end;
    }
}

// Exact-fp32 fallback for shapes the fast path can't handle.
__global__ void naive_kernel(const float* __restrict__ f,
                             const int* __restrict__ tri,
                             const float* __restrict__ w,
                             float* __restrict__ out,
                             int B, int N, int M) {
    int m = blockIdx.x * blockDim.x + threadIdx.x;
    if (m >= M) return;
    int i0 = tri[3 * m], i1 = tri[3 * m + 1], i2 = tri[3 * m + 2];
    float w0 = w[3 * m], w1 = w[3 * m + 1], w2 = w[3 * m + 2];
    for (int b = 0; b < B; b++) {
        out[(long long)b * M + m] =
            w0 * f[(long long)b * N + i0] +
            w1 * f[(long long)b * N + i1] +
            w2 * f[(long long)b * N + i2];
    }
}

extern "C" void kernel_launch(void* const* d_in, const int* in_sizes, int n_in,
                              void* d_out, int out_size) {
    const float* f   = (const float*)d_in[0];
    const int*   tri = (const int*)d_in[1];
    const float* w   = (const float*)d_in[2];
    float* out = (float*)d_out;

    const int M = in_sizes[1] / 3;
    const int B = out_size / M;
    const int N = in_sizes[0] / B;

    const bool fast = (B % BB == 0) && (N <= 14000) &&
                      (M <= MAX_M) && (M % 4 == 0);

    if (!fast) {
        naive_kernel<<<(M + 255) / 256, 256>>>(f, tri, w, out, B, N, M);
        return;
    }

    pack_kernel<<<(M + 255) / 256, 256>>>(tri, w, M);

    int sms = 148;
    cudaDeviceGetAttribute(&sms, cudaDevAttrMultiProcessorCount, 0);

    const int smem_bytes = BB * N * (int)sizeof(__half);   // 80 KB at N=10000
    cudaFuncSetAttribute(interp_kernel,
                         cudaFuncAttributeMaxDynamicSharedMemorySize, smem_bytes);

    const int grid = 2 * sms;   // 2 blocks resident per SM, single wave
    interp_kernel<<<grid, 768, smem_bytes>>>(f, out, B, N, M);
}